// round 16
// baseline (speedup 1.0000x reference)
#include <cuda_runtime.h>
#include <cuda_fp16.h>
#include <cstdint>

// ---------------------------------------------------------------------------
// MambaBlock: B=2, L=1024, Dm=1024, Di=2048, Nstate=64, Kconv=4
// v16: = v13 (best passing) with BK=64 GEMM k-tiles (half the barriers,
//      64-MMA bursts between syncs). Scan = v13 smem-staged 16ch/block.
// ---------------------------------------------------------------------------

#define BATCH 2
#define SEQ   1024
#define DM    1024
#define DI    2048
#define NST   64
#define KCONV 4
#define ROWS  (BATCH * SEQ)   // 2048

__device__ float  g_xi  [ROWS * DI];
__device__ float  g_sres[ROWS * DI];
__device__ float  g_dt  [ROWS * DI];
__device__ float  g_xc  [ROWS * DI];
__device__ float  g_B   [(ROWS + 1) * NST];

__device__ __half g_xn_h[ROWS * DM];
__device__ __half g_w1_h[2 * DI * DM];
__device__ __half g_xc_h[ROWS * DI];
__device__ __half g_dw_h[DI * DI];
__device__ __half g_z_h [ROWS * DI];
__device__ __half g_ow_h[DM * DI];

__device__ __forceinline__ float siluf(float x) { return x / (1.0f + __expf(-x)); }
__device__ __forceinline__ float softplusf(float x) {
    return fmaxf(x, 0.0f) + log1pf(__expf(-fabsf(x)));
}
__device__ __forceinline__ float ex2f(float x) {
    float r;
    asm("ex2.approx.f32 %0, %1;" : "=f"(r) : "f"(x));
    return r;
}

__device__ __forceinline__ uint32_t smem_u32(const void* p) {
    uint32_t r;
    asm("{ .reg .u64 t; cvta.to.shared.u64 t, %1; cvt.u32.u64 %0, t; }" : "=r"(r) : "l"(p));
    return r;
}

#define CP_ASYNC16(dst, src) \
    asm volatile("cp.async.cg.shared.global [%0], [%1], 16;" :: "r"(dst), "l"(src))
#define CP_COMMIT() asm volatile("cp.async.commit_group;" ::: "memory")
#define CP_WAIT1()  asm volatile("cp.async.wait_group 1;" ::: "memory")

#define LDSM4(r0, r1, r2, r3, a) \
    asm volatile("ldmatrix.sync.aligned.m8n8.x4.shared.b16 {%0,%1,%2,%3}, [%4];" \
        : "=r"(r0), "=r"(r1), "=r"(r2), "=r"(r3) : "r"(a))
#define LDSM2(r0, r1, a) \
    asm volatile("ldmatrix.sync.aligned.m8n8.x2.shared.b16 {%0,%1}, [%2];" \
        : "=r"(r0), "=r"(r1) : "r"(a))

#define MMA16816(d, a, b) \
    asm volatile("mma.sync.aligned.m16n8k16.row.col.f32.f16.f16.f32 " \
        "{%0,%1,%2,%3}, {%4,%5,%6,%7}, {%8,%9}, {%0,%1,%2,%3};" \
        : "+f"((d)[0]), "+f"((d)[1]), "+f"((d)[2]), "+f"((d)[3]) \
        : "r"((a)[0]), "r"((a)[1]), "r"((a)[2]), "r"((a)[3]), "r"((b)[0]), "r"((b)[1]))

// ============================ mma GEMM =====================================
// C[m,n] = sum_k A[m,k]*B[n,k], fp16 operands, fp32 accum.
// Block 128x128, BK=64, 3-stage cp.async ring, 256 threads, 2 CTAs/SM.
// 8 warps (2m x 4n), warp tile 64x32. One __syncthreads per 64-wide k-tile.
// EPI: 1 = softplus(v+bias[n]); 2 = v + add[m*N+n];
//      3 = bn<DI: C = v (xi); else D2 = silu(v)
#define MM_BK    64
#define MM_PAD   72                          // 144 B rows (conflict-free ldsm)
#define MM_ARR   (128 * MM_PAD * 2)          // 18432 B
#define MM_STAGE (2 * MM_ARR)                // 36864 B
#define MM_SMEM  (3 * MM_STAGE)              // 110592 B

template<int EPI>
__global__ __launch_bounds__(256, 2) void mma_gemm(
    const __half* __restrict__ A, const __half* __restrict__ B,
    float* __restrict__ C, float* __restrict__ D2,
    int M, int N, int K,
    const float* __restrict__ bias, const float* __restrict__ add)
{
    extern __shared__ char smem[];
    const uint32_t sb = smem_u32(smem);
    const int tid  = threadIdx.x;
    const int wid  = tid >> 5;
    const int lane = tid & 31;
    const int wm   = wid >> 2;
    const int wn   = wid & 3;
    const int bm   = blockIdx.y * 128, bn = blockIdx.x * 128;

    // loaders: row = tid>>1 (0..127), half = (tid&1)*32 elems (64 B = 4 chunks)
    const int lrow = tid >> 1;
    const int lcol = (tid & 1) * 32;
    const __half* gA = A + (size_t)(bm + lrow) * K + lcol;
    const __half* gB = B + (size_t)(bn + lrow) * K + lcol;
    const uint32_t ldst = (uint32_t)(lrow * MM_PAD + lcol) * 2;

    const int KT = K / MM_BK;
    const uint32_t a_off = (uint32_t)((wm * 64 + (lane & 15)) * MM_PAD + (lane >> 4) * 8) * 2;
    const uint32_t b_off = (uint32_t)((wn * 32 + (lane & 7)) * MM_PAD
                                      + ((lane >> 3) & 1) * 8) * 2;

    float acc[16][4];
    #pragma unroll
    for (int i = 0; i < 16; i++)
        #pragma unroll
        for (int j = 0; j < 4; j++) acc[i][j] = 0.0f;

    auto load_stage = [&](int st, int k0) {
        const uint32_t sa = sb + (uint32_t)st * MM_STAGE;
        #pragma unroll
        for (int c = 0; c < 4; c++) {
            CP_ASYNC16(sa + ldst + c * 16,          gA + k0 + c * 8);
            CP_ASYNC16(sa + MM_ARR + ldst + c * 16, gB + k0 + c * 8);
        }
    };

    load_stage(0, 0);     CP_COMMIT();
    load_stage(1, MM_BK); CP_COMMIT();

    int st = 0;
    for (int kt = 0; kt < KT; kt++) {
        CP_WAIT1();
        __syncthreads();
        const uint32_t stb = sb + (uint32_t)st * MM_STAGE;

        #pragma unroll
        for (int ks = 0; ks < 4; ks++) {
            const uint32_t kb = (uint32_t)(ks * 16) * 2;
            uint32_t ah[4][4], bh[4][2];
            #pragma unroll
            for (int mi = 0; mi < 4; mi++) {
                const uint32_t ao = stb + a_off + (uint32_t)(mi * 16 * MM_PAD) * 2 + kb;
                LDSM4(ah[mi][0], ah[mi][1], ah[mi][2], ah[mi][3], ao);
            }
            #pragma unroll
            for (int ni = 0; ni < 4; ni++) {
                const uint32_t bo = stb + MM_ARR + b_off
                                  + (uint32_t)(ni * 8 * MM_PAD) * 2 + kb;
                LDSM2(bh[ni][0], bh[ni][1], bo);
            }
            #pragma unroll
            for (int mi = 0; mi < 4; mi++)
                #pragma unroll
                for (int ni = 0; ni < 4; ni++)
                    MMA16816(acc[mi * 4 + ni], ah[mi], bh[ni]);
        }

        if (kt + 2 < KT) load_stage((st + 2) % 3, (kt + 2) * MM_BK);
        CP_COMMIT();
        st = (st + 1) % 3;
    }

    const int g  = lane >> 2;
    const int tc = (lane & 3) * 2;
    #pragma unroll
    for (int mi = 0; mi < 4; mi++) {
        #pragma unroll
        for (int ni = 0; ni < 4; ni++) {
            const float* a4 = acc[mi * 4 + ni];
            const int n = bn + wn * 32 + ni * 8 + tc;
            #pragma unroll
            for (int half_ = 0; half_ < 2; half_++) {
                const int m = bm + wm * 64 + mi * 16 + g + half_ * 8;
                float2 v = make_float2(a4[half_ * 2], a4[half_ * 2 + 1]);
                if (EPI == 1) {
                    v.x = softplusf(v.x + bias[n]);
                    v.y = softplusf(v.y + bias[n + 1]);
                    *(float2*)&C[(size_t)m * N + n] = v;
                } else if (EPI == 2) {
                    float2 s = *(const float2*)&add[(size_t)m * N + n];
                    v.x += s.x; v.y += s.y;
                    *(float2*)&C[(size_t)m * N + n] = v;
                } else { // EPI == 3
                    if (bn < DI) {
                        *(float2*)&C[(size_t)m * DI + n] = v;
                    } else {
                        float2 sv = make_float2(siluf(v.x), siluf(v.y));
                        *(float2*)&D2[(size_t)m * DI + (n - DI)] = sv;
                    }
                }
            }
        }
    }
}

// ============================ small kernels ================================

__global__ __launch_bounds__(256) void rmsnorm_kernel(
    const float* __restrict__ x, const float* __restrict__ w,
    __half* __restrict__ xh)
{
    int row = blockIdx.x, tid = threadIdx.x;
    const float* xr = x + (size_t)row * DM;
    float s = 0.0f;
    for (int i = tid; i < DM; i += 256) { float v = xr[i]; s += v * v; }
    #pragma unroll
    for (int o = 16; o > 0; o >>= 1) s += __shfl_down_sync(0xffffffffu, s, o);
    __shared__ float sm[8];
    if ((tid & 31) == 0) sm[tid >> 5] = s;
    __syncthreads();
    if (tid == 0) {
        float t = 0.0f;
        #pragma unroll
        for (int i = 0; i < 8; i++) t += sm[i];
        sm[0] = rsqrtf(t / (float)DM + 1e-6f);
    }
    __syncthreads();
    float inv = sm[0];
    for (int i = tid; i < DM; i += 256)
        xh[(size_t)row * DM + i] = __float2half(w[i] * xr[i] * inv);
}

__global__ __launch_bounds__(256) void cvt_f2h_kernel(
    const float* __restrict__ in, __half* __restrict__ out, int n4)
{
    int i = blockIdx.x * 256 + threadIdx.x;
    if (i >= n4) return;
    float4 v = *(const float4*)(in + (size_t)i * 4);
    __half2 p0 = __floats2half2_rn(v.x, v.y);
    __half2 p1 = __floats2half2_rn(v.z, v.w);
    *(uint2*)(out + (size_t)i * 4) = make_uint2(*(uint32_t*)&p0, *(uint32_t*)&p1);
}

__global__ __launch_bounds__(256) void conv_silu_kernel(
    const float* __restrict__ xi, const float* __restrict__ cw,
    const float* __restrict__ cb, float* __restrict__ xc,
    __half* __restrict__ xch)
{
    int idx = blockIdx.x * 256 + threadIdx.x;
    int c  = idx & (DI - 1);
    int bl = idx >> 11;
    int l  = bl & (SEQ - 1);
    int b  = bl >> 10;

    float acc = cb[c];
    #pragma unroll
    for (int k = 0; k < KCONV; k++) {
        int lp = l - (KCONV - 1) + k;
        if (lp >= 0)
            acc = fmaf(xi[((size_t)(b * SEQ + lp)) * DI + c], cw[c * KCONV + k], acc);
    }
    float v = siluf(acc);
    xc[(size_t)bl * DI + c]  = v;
    xch[(size_t)bl * DI + c] = __float2half(v);
}

#define GBM 128
#define GBK 16
#define SK_SLICES 16
#define SK_KLEN   (DI / SK_SLICES)

__global__ __launch_bounds__(256) void gemm_skinny64_splitk(
    const float* __restrict__ A, const float* __restrict__ B, float* __restrict__ C,
    int K)
{
    __shared__ float As[GBK][GBM + 4];
    __shared__ float Bs[GBK][64 + 4];

    const int tid = threadIdx.x;
    const int bm  = blockIdx.y * GBM;
    const int kb  = blockIdx.x * SK_KLEN;
    const int tx  = tid & 15;
    const int ty  = tid >> 4;
    const int lr  = tid >> 1;
    const int lc  = (tid & 1) * 8;
    const int lrB = tid >> 2;
    const int lcB = (tid & 3) * 4;

    const float* Aptr = A + (size_t)(bm + lr) * K + kb + lc;
    const float* Bptr = B + (size_t)lrB * K + kb + lcB;

    float acc[8][4];
    #pragma unroll
    for (int i = 0; i < 8; i++)
        #pragma unroll
        for (int j = 0; j < 4; j++) acc[i][j] = 0.0f;

    for (int k0 = 0; k0 < SK_KLEN; k0 += GBK) {
        float4 a0 = *(const float4*)(Aptr + k0);
        float4 a1 = *(const float4*)(Aptr + k0 + 4);
        float4 b0 = *(const float4*)(Bptr + k0);
        As[lc + 0][lr] = a0.x; As[lc + 1][lr] = a0.y;
        As[lc + 2][lr] = a0.z; As[lc + 3][lr] = a0.w;
        As[lc + 4][lr] = a1.x; As[lc + 5][lr] = a1.y;
        As[lc + 6][lr] = a1.z; As[lc + 7][lr] = a1.w;
        Bs[lcB + 0][lrB] = b0.x; Bs[lcB + 1][lrB] = b0.y;
        Bs[lcB + 2][lrB] = b0.z; Bs[lcB + 3][lrB] = b0.w;
        __syncthreads();
        #pragma unroll
        for (int k = 0; k < GBK; k++) {
            float4 av0 = *(const float4*)&As[k][ty * 8];
            float4 av1 = *(const float4*)&As[k][ty * 8 + 4];
            float4 bv0 = *(const float4*)&Bs[k][tx * 4];
            float av[8] = {av0.x, av0.y, av0.z, av0.w, av1.x, av1.y, av1.z, av1.w};
            float bv[4] = {bv0.x, bv0.y, bv0.z, bv0.w};
            #pragma unroll
            for (int i = 0; i < 8; i++)
                #pragma unroll
                for (int j = 0; j < 4; j++)
                    acc[i][j] = fmaf(av[i], bv[j], acc[i][j]);
        }
        __syncthreads();
    }
    #pragma unroll
    for (int i = 0; i < 8; i++) {
        int m = bm + ty * 8 + i;
        #pragma unroll
        for (int j = 0; j < 4; j++)
            atomicAdd(&C[(size_t)m * NST + tx * 4 + j], acc[i][j]);
    }
}

// ============================ scan (v13) ===================================
#define SCH    16
#define SCHUNK 128
#define NCH    (SEQ / SCHUNK)
#define SC_BBUF  (SCHUNK * NST * 4)
#define SC_PLANE (SCH * SCHUNK * 4)
#define SC_STAGE (SC_BBUF + 3 * SC_PLANE)
#define SC_SMEM  (2 * SC_STAGE)

__global__ __launch_bounds__(512) void scan_kernel(
    const float* __restrict__ dtb, const float* __restrict__ xcb,
    const float* __restrict__ srb, const float* __restrict__ Bs,
    const float* __restrict__ A_log, const float* __restrict__ Dp,
    __half* __restrict__ zh)
{
    extern __shared__ char smem[];
    float* smf = (float*)smem;
    const uint32_t sb = smem_u32(smem);
    const int tid  = threadIdx.x;
    const int wid  = tid >> 5;
    const int lane = tid & 31;
    const int b    = blockIdx.x >> 7;
    const int c0   = (blockIdx.x & 127) * SCH;
    const int c    = c0 + wid;

    const float LOG2E = 1.4426950408889634f;
    const float a0 = -expf(A_log[c * NST + 2 * lane + 0]) * LOG2E;
    const float a1 = -expf(A_log[c * NST + 2 * lane + 1]) * LOG2E;
    float h0 = 0.f, h1 = 0.f;
    const float Dc = Dp[c];

    const float* B_g  = Bs  + (size_t)(b * SEQ) * NST;
    const float* dt_g = dtb + (size_t)(b * SEQ) * DI;
    const float* xc_g = xcb + (size_t)(b * SEQ) * DI;
    const float* sr_g = srb + (size_t)(b * SEQ) * DI;
    __half* z_p = zh + (size_t)(b * SEQ) * DI + c;

    auto load_chunk = [&](int st, int l0) {
        const uint32_t sB = sb + (uint32_t)st * SC_STAGE;
        #pragma unroll
        for (int r = 0; r < 4; r++) {
            const int i = tid + r * 512;
            const int s = i >> 4, j = i & 15;
            CP_ASYNC16(sB + (uint32_t)i * 16, &B_g[(size_t)(l0 + s) * NST + j * 4]);
        }
        const int s = tid >> 2, hh = (tid & 3) * 4;
        const size_t go = (size_t)(l0 + s) * DI + c0 + hh;
        CP_ASYNC16(sB + SC_BBUF                 + (uint32_t)tid * 16, &dt_g[go]);
        CP_ASYNC16(sB + SC_BBUF +     SC_PLANE  + (uint32_t)tid * 16, &xc_g[go]);
        CP_ASYNC16(sB + SC_BBUF + 2 * SC_PLANE  + (uint32_t)tid * 16, &sr_g[go]);
    };

    load_chunk(0, 0);      CP_COMMIT();
    load_chunk(1, SCHUNK); CP_COMMIT();

    for (int k = 0; k < NCH; k++) {
        CP_WAIT1();
        __syncthreads();
        const int st = k & 1;
        const int fB  = st * (SC_STAGE / 4);
        const int fDT = fB + SC_BBUF / 4;
        const int fXC = fDT + SC_PLANE / 4;
        const int fSR = fXC + SC_PLANE / 4;
        const int l0 = k * SCHUNK;

        #pragma unroll 4
        for (int s = 0; s < SCHUNK; s++) {
            float dtv = smf[fDT + s * SCH + wid];
            float xv  = smf[fXC + s * SCH + wid];
            float rv  = smf[fSR + s * SCH + wid];
            float2 Bv = *(const float2*)&smf[fB + s * NST + lane * 2];
            h0 = fmaf(ex2f(a0 * dtv), h0, Bv.x * xv);
            h1 = fmaf(ex2f(a1 * dtv), h1, Bv.y * xv);
            float y = h0 + h1;
            y += __shfl_down_sync(0xffffffffu, y, 16);
            y += __shfl_down_sync(0xffffffffu, y, 8);
            y += __shfl_down_sync(0xffffffffu, y, 4);
            y += __shfl_down_sync(0xffffffffu, y, 2);
            y += __shfl_down_sync(0xffffffffu, y, 1);
            if (lane == 0)
                z_p[(size_t)(l0 + s) * DI] = __float2half(fmaf(Dc, xv, y) * rv);
        }
        __syncthreads();

        if (k + 2 < NCH) load_chunk(st, (k + 2) * SCHUNK);
        CP_COMMIT();
    }
}

// ---------------------------------------------------------------------------
extern "C" void kernel_launch(void* const* d_in, const int* in_sizes, int n_in,
                              void* d_out, int out_size)
{
    const float* x        = (const float*)d_in[0];
    const float* norm_w   = (const float*)d_in[1];
    const float* in_proj  = (const float*)d_in[2];
    const float* conv_w   = (const float*)d_in[3];
    const float* conv_b   = (const float*)d_in[4];
    const float* x_proj   = (const float*)d_in[5];
    const float* dt_w     = (const float*)d_in[6];
    const float* dt_b     = (const float*)d_in[7];
    const float* A_log    = (const float*)d_in[8];
    const float* D_param  = (const float*)d_in[9];
    const float* out_proj = (const float*)d_in[10];
    float* out = (float*)d_out;

    float *xi, *sres, *dtb, *xc, *Bssm;
    __half *xnh, *w1h, *xch, *dwh, *zh, *owh;
    cudaGetSymbolAddress((void**)&xi,   g_xi);
    cudaGetSymbolAddress((void**)&sres, g_sres);
    cudaGetSymbolAddress((void**)&dtb,  g_dt);
    cudaGetSymbolAddress((void**)&xc,   g_xc);
    cudaGetSymbolAddress((void**)&Bssm, g_B);
    cudaGetSymbolAddress((void**)&xnh,  g_xn_h);
    cudaGetSymbolAddress((void**)&w1h,  g_w1_h);
    cudaGetSymbolAddress((void**)&xch,  g_xc_h);
    cudaGetSymbolAddress((void**)&dwh,  g_dw_h);
    cudaGetSymbolAddress((void**)&zh,   g_z_h);
    cudaGetSymbolAddress((void**)&owh,  g_ow_h);

    cudaFuncSetAttribute((const void*)mma_gemm<1>,
                         cudaFuncAttributeMaxDynamicSharedMemorySize, MM_SMEM);
    cudaFuncSetAttribute((const void*)mma_gemm<2>,
                         cudaFuncAttributeMaxDynamicSharedMemorySize, MM_SMEM);
    cudaFuncSetAttribute((const void*)mma_gemm<3>,
                         cudaFuncAttributeMaxDynamicSharedMemorySize, MM_SMEM);
    cudaFuncSetAttribute((const void*)scan_kernel,
                         cudaFuncAttributeMaxDynamicSharedMemorySize, SC_SMEM);

    cudaMemsetAsync(Bssm, 0, (size_t)ROWS * NST * sizeof(float), 0);

    cvt_f2h_kernel<<<(2*DI*DM/4 + 255)/256, 256>>>(in_proj, w1h, 2*DI*DM/4);
    rmsnorm_kernel<<<ROWS, 256>>>(x, norm_w, xnh);
    cvt_f2h_kernel<<<(DI*DI/4 + 255)/256, 256>>>(dt_w, dwh, DI*DI/4);

    // GEMM1 (EPI=3): n<DI -> xi; n>=DI -> silu -> sres
    mma_gemm<3><<<dim3(2*DI/128, ROWS/128), 256, MM_SMEM>>>(
        xnh, w1h, xi, sres, ROWS, 2*DI, DM, nullptr, nullptr);

    conv_silu_kernel<<<ROWS * DI / 256, 256>>>(xi, conv_w, conv_b, xc, xch);

    // GEMM2 (EPI=1): dt = softplus(..)
    mma_gemm<1><<<dim3(DI/128, ROWS/128), 256, MM_SMEM>>>(
        xch, dwh, dtb, nullptr, ROWS, DI, DI, dt_b, nullptr);

    cvt_f2h_kernel<<<(DM*DI/4 + 255)/256, 256>>>(out_proj, owh, DM*DI/4);

    gemm_skinny64_splitk<<<dim3(SK_SLICES, ROWS/GBM), 256>>>(
        xc, x_proj + (size_t)NST * DI, Bssm, DI);

    // scan + gate -> z fp16 (256 blocks x 512 threads)
    scan_kernel<<<256, 512, SC_SMEM>>>(dtb, xc, sres, Bssm, A_log, D_param, zh);

    // GEMM3 (EPI=2): out = z @ out_proj^T + x  (r13 shape)
    mma_gemm<2><<<dim3(DM/128, ROWS/128), 256, MM_SMEM>>>(
        zh, owh, out, nullptr, ROWS, DM, DI, nullptr, x);
}

// round 17
// speedup vs baseline: 1.2203x; 1.2203x over previous
#include <cuda_runtime.h>
#include <cuda_fp16.h>
#include <cstdint>

// ---------------------------------------------------------------------------
// MambaBlock: B=2, L=1024, Dm=1024, Di=2048, Nstate=64, Kconv=4
// v17: GEMMs = exact r13 config (best measured). Scan = 2 channels/warp,
//      16 lanes/ch, 4 states/lane (halves MIO wavefronts per channel-step).
// ---------------------------------------------------------------------------

#define BATCH 2
#define SEQ   1024
#define DM    1024
#define DI    2048
#define NST   64
#define KCONV 4
#define ROWS  (BATCH * SEQ)   // 2048

__device__ float  g_xi  [ROWS * DI];
__device__ float  g_sres[ROWS * DI];
__device__ float  g_dt  [ROWS * DI];
__device__ float  g_xc  [ROWS * DI];
__device__ float  g_B   [(ROWS + 1) * NST];

__device__ __half g_xn_h[ROWS * DM];
__device__ __half g_w1_h[2 * DI * DM];
__device__ __half g_xc_h[ROWS * DI];
__device__ __half g_dw_h[DI * DI];
__device__ __half g_z_h [ROWS * DI];
__device__ __half g_ow_h[DM * DI];

__device__ __forceinline__ float siluf(float x) { return x / (1.0f + __expf(-x)); }
__device__ __forceinline__ float softplusf(float x) {
    return fmaxf(x, 0.0f) + log1pf(__expf(-fabsf(x)));
}
__device__ __forceinline__ float ex2f(float x) {
    float r;
    asm("ex2.approx.f32 %0, %1;" : "=f"(r) : "f"(x));
    return r;
}

__device__ __forceinline__ uint32_t smem_u32(const void* p) {
    uint32_t r;
    asm("{ .reg .u64 t; cvta.to.shared.u64 t, %1; cvt.u32.u64 %0, t; }" : "=r"(r) : "l"(p));
    return r;
}

#define CP_ASYNC16(dst, src) \
    asm volatile("cp.async.cg.shared.global [%0], [%1], 16;" :: "r"(dst), "l"(src))
#define CP_COMMIT() asm volatile("cp.async.commit_group;" ::: "memory")
#define CP_WAIT1()  asm volatile("cp.async.wait_group 1;" ::: "memory")

#define LDSM4(r0, r1, r2, r3, a) \
    asm volatile("ldmatrix.sync.aligned.m8n8.x4.shared.b16 {%0,%1,%2,%3}, [%4];" \
        : "=r"(r0), "=r"(r1), "=r"(r2), "=r"(r3) : "r"(a))
#define LDSM2(r0, r1, a) \
    asm volatile("ldmatrix.sync.aligned.m8n8.x2.shared.b16 {%0,%1}, [%2];" \
        : "=r"(r0), "=r"(r1) : "r"(a))

#define MMA16816(d, a, b) \
    asm volatile("mma.sync.aligned.m16n8k16.row.col.f32.f16.f16.f32 " \
        "{%0,%1,%2,%3}, {%4,%5,%6,%7}, {%8,%9}, {%0,%1,%2,%3};" \
        : "+f"((d)[0]), "+f"((d)[1]), "+f"((d)[2]), "+f"((d)[3]) \
        : "r"((a)[0]), "r"((a)[1]), "r"((a)[2]), "r"((a)[3]), "r"((b)[0]), "r"((b)[1]))

// ============================ mma GEMM (r13 config) ========================
#define MM_BK    32
#define MM_PAD   40
#define MM_AARR  (128 * MM_PAD * 2)
#define MM_STAGE (2 * MM_AARR)
#define MM_SMEM  (3 * MM_STAGE)

template<int EPI>
__global__ __launch_bounds__(256, 2) void mma_gemm(
    const __half* __restrict__ A, const __half* __restrict__ B,
    float* __restrict__ C, float* __restrict__ D2,
    int M, int N, int K,
    const float* __restrict__ bias, const float* __restrict__ add)
{
    extern __shared__ char smem[];
    const uint32_t sb = smem_u32(smem);
    const int tid  = threadIdx.x;
    const int wid  = tid >> 5;
    const int lane = tid & 31;
    const int wm   = wid >> 2;
    const int wn   = wid & 3;
    const int bm   = blockIdx.y * 128, bn = blockIdx.x * 128;

    const int lrow = tid >> 1;
    const int lcol = (tid & 1) * 16;
    const __half* gA = A + (size_t)(bm + lrow) * K + lcol;
    const __half* gB = B + (size_t)(bn + lrow) * K + lcol;
    const uint32_t ldst = (uint32_t)(lrow * MM_PAD + lcol) * 2;

    const int KT = K / MM_BK;
    const uint32_t a_off = (uint32_t)((wm * 64 + (lane & 15)) * MM_PAD + (lane >> 4) * 8) * 2;
    const uint32_t b_off = (uint32_t)((wn * 32 + (lane & 7)) * MM_PAD
                                      + ((lane >> 3) & 1) * 8) * 2;

    float acc[16][4];
    #pragma unroll
    for (int i = 0; i < 16; i++)
        #pragma unroll
        for (int j = 0; j < 4; j++) acc[i][j] = 0.0f;

    auto load_stage = [&](int st, int k0) {
        const uint32_t sa = sb + (uint32_t)st * MM_STAGE;
        CP_ASYNC16(sa + ldst,                 gA + k0);
        CP_ASYNC16(sa + ldst + 16,            gA + k0 + 8);
        CP_ASYNC16(sa + MM_AARR + ldst,       gB + k0);
        CP_ASYNC16(sa + MM_AARR + ldst + 16,  gB + k0 + 8);
    };

    load_stage(0, 0);     CP_COMMIT();
    load_stage(1, MM_BK); CP_COMMIT();

    int st = 0;
    for (int kt = 0; kt < KT; kt++) {
        CP_WAIT1();
        __syncthreads();
        const uint32_t stb = sb + (uint32_t)st * MM_STAGE;

        #pragma unroll
        for (int ks = 0; ks < 2; ks++) {
            const uint32_t kb = (uint32_t)(ks * 16) * 2;
            uint32_t ah[4][4], bh[4][2];
            #pragma unroll
            for (int mi = 0; mi < 4; mi++) {
                const uint32_t ao = stb + a_off + (uint32_t)(mi * 16 * MM_PAD) * 2 + kb;
                LDSM4(ah[mi][0], ah[mi][1], ah[mi][2], ah[mi][3], ao);
            }
            #pragma unroll
            for (int ni = 0; ni < 4; ni++) {
                const uint32_t bo = stb + MM_AARR + b_off
                                  + (uint32_t)(ni * 8 * MM_PAD) * 2 + kb;
                LDSM2(bh[ni][0], bh[ni][1], bo);
            }
            #pragma unroll
            for (int mi = 0; mi < 4; mi++)
                #pragma unroll
                for (int ni = 0; ni < 4; ni++)
                    MMA16816(acc[mi * 4 + ni], ah[mi], bh[ni]);
        }

        if (kt + 2 < KT) load_stage((st + 2) % 3, (kt + 2) * MM_BK);
        CP_COMMIT();
        st = (st + 1) % 3;
    }

    const int g  = lane >> 2;
    const int tc = (lane & 3) * 2;
    #pragma unroll
    for (int mi = 0; mi < 4; mi++) {
        #pragma unroll
        for (int ni = 0; ni < 4; ni++) {
            const float* a4 = acc[mi * 4 + ni];
            const int n = bn + wn * 32 + ni * 8 + tc;
            #pragma unroll
            for (int half_ = 0; half_ < 2; half_++) {
                const int m = bm + wm * 64 + mi * 16 + g + half_ * 8;
                float2 v = make_float2(a4[half_ * 2], a4[half_ * 2 + 1]);
                if (EPI == 1) {
                    v.x = softplusf(v.x + bias[n]);
                    v.y = softplusf(v.y + bias[n + 1]);
                    *(float2*)&C[(size_t)m * N + n] = v;
                } else if (EPI == 2) {
                    float2 s = *(const float2*)&add[(size_t)m * N + n];
                    v.x += s.x; v.y += s.y;
                    *(float2*)&C[(size_t)m * N + n] = v;
                } else { // EPI == 3
                    if (bn < DI) {
                        *(float2*)&C[(size_t)m * DI + n] = v;
                    } else {
                        float2 sv = make_float2(siluf(v.x), siluf(v.y));
                        *(float2*)&D2[(size_t)m * DI + (n - DI)] = sv;
                    }
                }
            }
        }
    }
}

// ============================ small kernels ================================

__global__ __launch_bounds__(256) void rmsnorm_kernel(
    const float* __restrict__ x, const float* __restrict__ w,
    __half* __restrict__ xh)
{
    int row = blockIdx.x, tid = threadIdx.x;
    const float* xr = x + (size_t)row * DM;
    float s = 0.0f;
    for (int i = tid; i < DM; i += 256) { float v = xr[i]; s += v * v; }
    #pragma unroll
    for (int o = 16; o > 0; o >>= 1) s += __shfl_down_sync(0xffffffffu, s, o);
    __shared__ float sm[8];
    if ((tid & 31) == 0) sm[tid >> 5] = s;
    __syncthreads();
    if (tid == 0) {
        float t = 0.0f;
        #pragma unroll
        for (int i = 0; i < 8; i++) t += sm[i];
        sm[0] = rsqrtf(t / (float)DM + 1e-6f);
    }
    __syncthreads();
    float inv = sm[0];
    for (int i = tid; i < DM; i += 256)
        xh[(size_t)row * DM + i] = __float2half(w[i] * xr[i] * inv);
}

__global__ __launch_bounds__(256) void cvt_f2h_kernel(
    const float* __restrict__ in, __half* __restrict__ out, int n4)
{
    int i = blockIdx.x * 256 + threadIdx.x;
    if (i >= n4) return;
    float4 v = *(const float4*)(in + (size_t)i * 4);
    __half2 p0 = __floats2half2_rn(v.x, v.y);
    __half2 p1 = __floats2half2_rn(v.z, v.w);
    *(uint2*)(out + (size_t)i * 4) = make_uint2(*(uint32_t*)&p0, *(uint32_t*)&p1);
}

__global__ __launch_bounds__(256) void conv_silu_kernel(
    const float* __restrict__ xi, const float* __restrict__ cw,
    const float* __restrict__ cb, float* __restrict__ xc,
    __half* __restrict__ xch)
{
    int idx = blockIdx.x * 256 + threadIdx.x;
    int c  = idx & (DI - 1);
    int bl = idx >> 11;
    int l  = bl & (SEQ - 1);
    int b  = bl >> 10;

    float acc = cb[c];
    #pragma unroll
    for (int k = 0; k < KCONV; k++) {
        int lp = l - (KCONV - 1) + k;
        if (lp >= 0)
            acc = fmaf(xi[((size_t)(b * SEQ + lp)) * DI + c], cw[c * KCONV + k], acc);
    }
    float v = siluf(acc);
    xc[(size_t)bl * DI + c]  = v;
    xch[(size_t)bl * DI + c] = __float2half(v);
}

#define GBM 128
#define GBK 16
#define SK_SLICES 16
#define SK_KLEN   (DI / SK_SLICES)

__global__ __launch_bounds__(256) void gemm_skinny64_splitk(
    const float* __restrict__ A, const float* __restrict__ B, float* __restrict__ C,
    int K)
{
    __shared__ float As[GBK][GBM + 4];
    __shared__ float Bs[GBK][64 + 4];

    const int tid = threadIdx.x;
    const int bm  = blockIdx.y * GBM;
    const int kb  = blockIdx.x * SK_KLEN;
    const int tx  = tid & 15;
    const int ty  = tid >> 4;
    const int lr  = tid >> 1;
    const int lc  = (tid & 1) * 8;
    const int lrB = tid >> 2;
    const int lcB = (tid & 3) * 4;

    const float* Aptr = A + (size_t)(bm + lr) * K + kb + lc;
    const float* Bptr = B + (size_t)lrB * K + kb + lcB;

    float acc[8][4];
    #pragma unroll
    for (int i = 0; i < 8; i++)
        #pragma unroll
        for (int j = 0; j < 4; j++) acc[i][j] = 0.0f;

    for (int k0 = 0; k0 < SK_KLEN; k0 += GBK) {
        float4 a0 = *(const float4*)(Aptr + k0);
        float4 a1 = *(const float4*)(Aptr + k0 + 4);
        float4 b0 = *(const float4*)(Bptr + k0);
        As[lc + 0][lr] = a0.x; As[lc + 1][lr] = a0.y;
        As[lc + 2][lr] = a0.z; As[lc + 3][lr] = a0.w;
        As[lc + 4][lr] = a1.x; As[lc + 5][lr] = a1.y;
        As[lc + 6][lr] = a1.z; As[lc + 7][lr] = a1.w;
        Bs[lcB + 0][lrB] = b0.x; Bs[lcB + 1][lrB] = b0.y;
        Bs[lcB + 2][lrB] = b0.z; Bs[lcB + 3][lrB] = b0.w;
        __syncthreads();
        #pragma unroll
        for (int k = 0; k < GBK; k++) {
            float4 av0 = *(const float4*)&As[k][ty * 8];
            float4 av1 = *(const float4*)&As[k][ty * 8 + 4];
            float4 bv0 = *(const float4*)&Bs[k][tx * 4];
            float av[8] = {av0.x, av0.y, av0.z, av0.w, av1.x, av1.y, av1.z, av1.w};
            float bv[4] = {bv0.x, bv0.y, bv0.z, bv0.w};
            #pragma unroll
            for (int i = 0; i < 8; i++)
                #pragma unroll
                for (int j = 0; j < 4; j++)
                    acc[i][j] = fmaf(av[i], bv[j], acc[i][j]);
        }
        __syncthreads();
    }
    #pragma unroll
    for (int i = 0; i < 8; i++) {
        int m = bm + ty * 8 + i;
        #pragma unroll
        for (int j = 0; j < 4; j++)
            atomicAdd(&C[(size_t)m * NST + tx * 4 + j], acc[i][j]);
    }
}

// ============================ scan =========================================
// Block = 512 threads = 16 warps, 2 channels/warp -> 32 channels/block,
// 128 blocks (single wave, 1 CTA/SM, 160 KB smem). 16 lanes per channel,
// 4 states/lane. B rows shared by both half-warps (and all warps).
// Per channel-step MIO: ~5 wavefronts (was ~10).
#define SCH    32                              // channels per block
#define SCHUNK 128
#define NCH    (SEQ / SCHUNK)                  // 8
#define SC_BBUF  (SCHUNK * NST * 4)            // 32768
#define SC_PLANE (SCH * SCHUNK * 4)            // 16384
#define SC_STAGE (SC_BBUF + 3 * SC_PLANE)      // 81920
#define SC_SMEM  (2 * SC_STAGE)                // 163840

__global__ __launch_bounds__(512) void scan_kernel(
    const float* __restrict__ dtb, const float* __restrict__ xcb,
    const float* __restrict__ srb, const float* __restrict__ Bs,
    const float* __restrict__ A_log, const float* __restrict__ Dp,
    __half* __restrict__ zh)
{
    extern __shared__ char smem[];
    float* smf = (float*)smem;
    const uint32_t sb = smem_u32(smem);
    const int tid  = threadIdx.x;
    const int wid  = tid >> 5;
    const int lane = tid & 31;
    const int b    = blockIdx.x >> 6;              // 0..1 (64 blocks/batch)
    const int c0   = (blockIdx.x & 63) * SCH;
    const int g    = lane >> 4;                    // half-warp -> channel
    const int sidx = lane & 15;                    // state group (4 states)
    const int c    = c0 + wid * 2 + g;

    const float LOG2E = 1.4426950408889634f;
    float a[4];
    #pragma unroll
    for (int j = 0; j < 4; j++)
        a[j] = -expf(A_log[c * NST + sidx * 4 + j]) * LOG2E;
    float h[4] = {0.f, 0.f, 0.f, 0.f};
    const float Dc = Dp[c];

    const float* B_g  = Bs  + (size_t)(b * SEQ) * NST;
    const float* dt_g = dtb + (size_t)(b * SEQ) * DI;
    const float* xc_g = xcb + (size_t)(b * SEQ) * DI;
    const float* sr_g = srb + (size_t)(b * SEQ) * DI;
    __half* z_p = zh + (size_t)(b * SEQ) * DI + c;

    // chunk loader (512 threads): B = 2048 x 16B (4 rounds);
    // each plane = 1024 x 16B (2 rounds): i -> s = i>>3, ch4 = (i&7)*4
    auto load_chunk = [&](int st, int l0) {
        const uint32_t sB = sb + (uint32_t)st * SC_STAGE;
        #pragma unroll
        for (int r = 0; r < 4; r++) {
            const int i = tid + r * 512;
            const int s = i >> 4, j = i & 15;
            CP_ASYNC16(sB + (uint32_t)i * 16, &B_g[(size_t)(l0 + s) * NST + j * 4]);
        }
        #pragma unroll
        for (int r = 0; r < 2; r++) {
            const int i = tid + r * 512;           // 0..1023
            const int s = i >> 3, c4 = (i & 7) * 4;
            const size_t go = (size_t)(l0 + s) * DI + c0 + c4;
            CP_ASYNC16(sB + SC_BBUF                + (uint32_t)i * 16, &dt_g[go]);
            CP_ASYNC16(sB + SC_BBUF +     SC_PLANE + (uint32_t)i * 16, &xc_g[go]);
            CP_ASYNC16(sB + SC_BBUF + 2 * SC_PLANE + (uint32_t)i * 16, &sr_g[go]);
        }
    };

    load_chunk(0, 0);      CP_COMMIT();
    load_chunk(1, SCHUNK); CP_COMMIT();

    const int chix = wid * 2 + g;                  // channel index within block
    for (int k = 0; k < NCH; k++) {
        CP_WAIT1();
        __syncthreads();
        const int st = k & 1;
        const int fB  = st * (SC_STAGE / 4);
        const int fDT = fB + SC_BBUF / 4;
        const int fXC = fDT + SC_PLANE / 4;
        const int fSR = fXC + SC_PLANE / 4;
        const int l0 = k * SCHUNK;

        #pragma unroll 4
        for (int s = 0; s < SCHUNK; s++) {
            float dtv = smf[fDT + s * SCH + chix];
            float xv  = smf[fXC + s * SCH + chix];
            float rv  = smf[fSR + s * SCH + chix];
            float4 Bv = *(const float4*)&smf[fB + s * NST + sidx * 4];
            h[0] = fmaf(ex2f(a[0] * dtv), h[0], Bv.x * xv);
            h[1] = fmaf(ex2f(a[1] * dtv), h[1], Bv.y * xv);
            h[2] = fmaf(ex2f(a[2] * dtv), h[2], Bv.z * xv);
            h[3] = fmaf(ex2f(a[3] * dtv), h[3], Bv.w * xv);
            float y = (h[0] + h[1]) + (h[2] + h[3]);
            // 16-lane tree per half-warp: lane0 sums 0..15, lane16 sums 16..31
            y += __shfl_down_sync(0xffffffffu, y, 8);
            y += __shfl_down_sync(0xffffffffu, y, 4);
            y += __shfl_down_sync(0xffffffffu, y, 2);
            y += __shfl_down_sync(0xffffffffu, y, 1);
            if (sidx == 0)
                z_p[(size_t)(l0 + s) * DI] = __float2half(fmaf(Dc, xv, y) * rv);
        }
        __syncthreads();

        if (k + 2 < NCH) load_chunk(st, (k + 2) * SCHUNK);
        CP_COMMIT();
    }
}

// ---------------------------------------------------------------------------
extern "C" void kernel_launch(void* const* d_in, const int* in_sizes, int n_in,
                              void* d_out, int out_size)
{
    const float* x        = (const float*)d_in[0];
    const float* norm_w   = (const float*)d_in[1];
    const float* in_proj  = (const float*)d_in[2];
    const float* conv_w   = (const float*)d_in[3];
    const float* conv_b   = (const float*)d_in[4];
    const float* x_proj   = (const float*)d_in[5];
    const float* dt_w     = (const float*)d_in[6];
    const float* dt_b     = (const float*)d_in[7];
    const float* A_log    = (const float*)d_in[8];
    const float* D_param  = (const float*)d_in[9];
    const float* out_proj = (const float*)d_in[10];
    float* out = (float*)d_out;

    float *xi, *sres, *dtb, *xc, *Bssm;
    __half *xnh, *w1h, *xch, *dwh, *zh, *owh;
    cudaGetSymbolAddress((void**)&xi,   g_xi);
    cudaGetSymbolAddress((void**)&sres, g_sres);
    cudaGetSymbolAddress((void**)&dtb,  g_dt);
    cudaGetSymbolAddress((void**)&xc,   g_xc);
    cudaGetSymbolAddress((void**)&Bssm, g_B);
    cudaGetSymbolAddress((void**)&xnh,  g_xn_h);
    cudaGetSymbolAddress((void**)&w1h,  g_w1_h);
    cudaGetSymbolAddress((void**)&xch,  g_xc_h);
    cudaGetSymbolAddress((void**)&dwh,  g_dw_h);
    cudaGetSymbolAddress((void**)&zh,   g_z_h);
    cudaGetSymbolAddress((void**)&owh,  g_ow_h);

    cudaFuncSetAttribute((const void*)mma_gemm<1>,
                         cudaFuncAttributeMaxDynamicSharedMemorySize, MM_SMEM);
    cudaFuncSetAttribute((const void*)mma_gemm<2>,
                         cudaFuncAttributeMaxDynamicSharedMemorySize, MM_SMEM);
    cudaFuncSetAttribute((const void*)mma_gemm<3>,
                         cudaFuncAttributeMaxDynamicSharedMemorySize, MM_SMEM);
    cudaFuncSetAttribute((const void*)scan_kernel,
                         cudaFuncAttributeMaxDynamicSharedMemorySize, SC_SMEM);

    cudaMemsetAsync(Bssm, 0, (size_t)ROWS * NST * sizeof(float), 0);

    cvt_f2h_kernel<<<(2*DI*DM/4 + 255)/256, 256>>>(in_proj, w1h, 2*DI*DM/4);
    rmsnorm_kernel<<<ROWS, 256>>>(x, norm_w, xnh);
    cvt_f2h_kernel<<<(DI*DI/4 + 255)/256, 256>>>(dt_w, dwh, DI*DI/4);

    // GEMM1 (EPI=3): n<DI -> xi; n>=DI -> silu -> sres
    mma_gemm<3><<<dim3(2*DI/128, ROWS/128), 256, MM_SMEM>>>(
        xnh, w1h, xi, sres, ROWS, 2*DI, DM, nullptr, nullptr);

    conv_silu_kernel<<<ROWS * DI / 256, 256>>>(xi, conv_w, conv_b, xc, xch);

    // GEMM2 (EPI=1): dt = softplus(..)
    mma_gemm<1><<<dim3(DI/128, ROWS/128), 256, MM_SMEM>>>(
        xch, dwh, dtb, nullptr, ROWS, DI, DI, dt_b, nullptr);

    cvt_f2h_kernel<<<(DM*DI/4 + 255)/256, 256>>>(out_proj, owh, DM*DI/4);

    gemm_skinny64_splitk<<<dim3(SK_SLICES, ROWS/GBM), 256>>>(
        xc, x_proj + (size_t)NST * DI, Bssm, DI);

    // scan + gate -> z fp16 (128 blocks x 512 threads, 2 ch/warp)
    scan_kernel<<<128, 512, SC_SMEM>>>(dtb, xc, sres, Bssm, A_log, D_param, zh);

    // GEMM3 (EPI=2): out = z @ out_proj^T + x
    mma_gemm<2><<<dim3(DM/128, ROWS/128), 256, MM_SMEM>>>(
        zh, owh, out, nullptr, ROWS, DM, DI, nullptr, x);
}